// round 14
// baseline (speedup 1.0000x reference)
#include <cuda_runtime.h>
#include <cuda_bf16.h>

#define NB   8
#define NN   1024
#define NC   64
#define OC   64
#define KP1  5
#define RPB  4
#define ROWS (NB*NN)      // 8192
#define YSTR (KP1*OC)     // 320

#define STREAM_BLKS (ROWS/RPB)     // 2048
#define GEMM_BLKS   (128*KP1*2)    // 1280
#define FUSED_BLKS  (STREAM_BLKS + GEMM_BLKS)   // 3328

// Scratch (static device globals; no allocations allowed)
__device__ __align__(16) float g_srcR[ROWS];
__device__ __align__(16) float g_srcI[ROWS];
__device__ __align__(16) float g_dstR[ROWS];
__device__ __align__(16) float g_dstI[ROWS];
__device__ __align__(16) float g_rden[ROWS];
__device__ __align__(16) float g_Yrr[ROWS*YSTR];
__device__ __align__(16) float g_Yii[ROWS*YSTR];
__device__ __align__(16) float g_SLr[ROWS*KP1];
__device__ __align__(16) float g_SLi[ROWS*KP1];

// ---- packed fp32x2 helpers (sm_103a FFMA2) --------------------------------
typedef unsigned long long u64t;
__device__ __forceinline__ u64t pk2(float lo, float hi) {
    u64t d; asm("mov.b64 %0,{%1,%2};" : "=l"(d) : "f"(lo), "f"(hi)); return d;
}
__device__ __forceinline__ void upk2(u64t v, float& lo, float& hi) {
    asm("mov.b64 {%0,%1},%2;" : "=f"(lo), "=f"(hi) : "l"(v));
}
__device__ __forceinline__ u64t fma2(u64t a, u64t b, u64t c) {
    u64t d; asm("fma.rn.f32x2 %0,%1,%2,%3;" : "=l"(d) : "l"(a), "l"(b), "l"(c)); return d;
}

// ---------------------------------------------------------------------------
// Kernel 1: per-row complex projections. One warp per (b,n) row. (R7 exact)
// ---------------------------------------------------------------------------
__global__ void k_src(const float* __restrict__ Xr, const float* __restrict__ Xi,
                      const float* __restrict__ awr, const float* __restrict__ awi,
                      const float* __restrict__ abr, const float* __restrict__ abi)
{
    int gt   = blockIdx.x * blockDim.x + threadIdx.x;
    int warp = gt >> 5;
    int lane = gt & 31;
    if (warp >= ROWS) return;

    const float* xr = Xr + (size_t)warp * NC;
    const float* xi = Xi + (size_t)warp * NC;
    float xr0 = xr[lane], xr1 = xr[lane+32];
    float xi0 = xi[lane], xi1 = xi[lane+32];

    float wsr0 = awr[lane],    wsr1 = awr[lane+32];
    float wdr0 = awr[64+lane], wdr1 = awr[96+lane];
    float wsi0 = awi[lane],    wsi1 = awi[lane+32];
    float wdi0 = awi[64+lane], wdi1 = awi[96+lane];

    float sr = xr0*wsr0 + xr1*wsr1 - xi0*wsi0 - xi1*wsi1;
    float si = xr0*wsi0 + xr1*wsi1 + xi0*wsr0 + xi1*wsr1;
    float dr = xr0*wdr0 + xr1*wdr1 - xi0*wdi0 - xi1*wdi1;
    float di = xr0*wdi0 + xr1*wdi1 + xi0*wdr0 + xi1*wdr1;

    #pragma unroll
    for (int off = 16; off > 0; off >>= 1) {
        sr += __shfl_down_sync(0xFFFFFFFFu, sr, off);
        si += __shfl_down_sync(0xFFFFFFFFu, si, off);
        dr += __shfl_down_sync(0xFFFFFFFFu, dr, off);
        di += __shfl_down_sync(0xFFFFFFFFu, di, off);
    }
    if (lane == 0) {
        g_srcR[warp] = sr + *abr;
        g_srcI[warp] = si + *abi;
        g_dstR[warp] = dr;
        g_dstI[warp] = di;
    }
}

// ---------------------------------------------------------------------------
// Kernel 2: softmax denominators (axis i per (b,j)); stores reciprocal.
// ---------------------------------------------------------------------------
__global__ void k_denom(const float* __restrict__ par_p, const float* __restrict__ pai_p)
{
    int gt   = blockIdx.x * blockDim.x + threadIdx.x;
    int warp = gt >> 5;
    int lane = gt & 31;
    if (warp >= ROWS) return;

    int b = warp >> 10;
    float dr = g_dstR[warp], di = g_dstI[warp];
    float par = *par_p, pai = *pai_p;
    const float* sRp = g_srcR + b*NN;
    const float* sIp = g_srcI + b*NN;

    float acc = 0.f;
    #pragma unroll 4
    for (int i = lane; i < NN; i += 32) {
        float sr = sRp[i] + dr;
        float si = sIp[i] + di;
        sr = sr >= 0.f ? sr : par*sr;
        si = si >= 0.f ? si : pai*si;
        float m2  = sr*sr + si*si;
        float mag = m2 > 0.f ? m2 * rsqrtf(m2) : 0.f;
        acc += __expf(mag);
    }
    #pragma unroll
    for (int off = 16; off > 0; off >>= 1)
        acc += __shfl_down_sync(0xFFFFFFFFu, acc, off);
    if (lane == 0) g_rden[warp] = 1.0f / acc;
}

// ---------------------------------------------------------------------------
// Kernel 3 (fused): L-stream blocks interleaved with Y-GEMM blocks.
// Stream: all-k loads up front (MLP 10), FMA all, then INTERLEAVED reduce
// (off outer, k inner -> 10 independent shfl chains per level).
// ---------------------------------------------------------------------------
__global__ void __launch_bounds__(256, 3)
k_fused(const float* __restrict__ L_r, const float* __restrict__ L_i,
        const float* __restrict__ Xr,  const float* __restrict__ Xi,
        const float* __restrict__ wr,  const float* __restrict__ wi,
        const float* __restrict__ par_p, const float* __restrict__ pai_p)
{
    __shared__ __align__(16) float As[64][64];
    __shared__ __align__(16) float Ws[64][64];
    __shared__ float shPR[8][RPB][KP1];
    __shared__ float shPI[8][RPB][KP1];

    const int bid = blockIdx.x;
    const int t   = threadIdx.x;

    const int g0 = (int)(((long long)bid       * GEMM_BLKS) / FUSED_BLKS);
    const int g1 = (int)(((long long)(bid + 1) * GEMM_BLKS) / FUSED_BLKS);

    if (g1 > g0) {
        // ================= GEMM part: Y[n,k,o] = X @ w[k] =================
        const int gb   = g0;
        const int part = gb / (GEMM_BLKS/2);
        const int rem  = gb % (GEMM_BLKS/2);
        const int k    = rem / 128;
        const int n0   = (rem % 128) * 64;

        const float* A = part ? Xi : Xr;
        const float* W = (part ? wi : wr) + (size_t)k * NC * OC;
        float*       Y = part ? g_Yii : g_Yrr;

        for (int idx = t; idx < 64*64; idx += 256) {
            int r = idx >> 6, c = idx & 63;
            As[r][c] = A[(size_t)(n0 + r) * NC + c];
            ((float*)Ws)[idx] = W[idx];
        }
        __syncthreads();

        const int oq = t & 15;
        const int rg = t >> 4;

        u64t acc[4][2];
        #pragma unroll
        for (int rr = 0; rr < 4; rr++) { acc[rr][0] = 0ULL; acc[rr][1] = 0ULL; }

        #pragma unroll 8
        for (int c = 0; c < 64; c++) {
            ulonglong2 wv = *(const ulonglong2*)&Ws[c][oq*4];
            #pragma unroll
            for (int rr = 0; rr < 4; rr++) {
                float a  = As[rg*4 + rr][c];
                u64t  a2 = pk2(a, a);
                acc[rr][0] = fma2(a2, wv.x, acc[rr][0]);
                acc[rr][1] = fma2(a2, wv.y, acc[rr][1]);
            }
        }

        #pragma unroll
        for (int rr = 0; rr < 4; rr++) {
            float4 v;
            upk2(acc[rr][0], v.x, v.y);
            upk2(acc[rr][1], v.z, v.w);
            *(float4*)&Y[(size_t)(n0 + rg*4 + rr) * YSTR + k*OC + oq*4] = v;
        }
        return;
    }

    // ================= stream part =================
    const int sb   = bid - g0;
    const int b    = sb >> 8;
    const int i0   = (sb & 255) * RPB;
    const int warp = t >> 5;
    const int lane = t & 31;

    const float par = *par_p;
    const float pai = *pai_p;

    const float4 dR = ((const float4*)(g_dstR + b*NN))[t];
    const float4 dI = ((const float4*)(g_dstI + b*NN))[t];
    const float4 rd = ((const float4*)(g_rden + b*NN))[t];

    const float drv[4] = {dR.x, dR.y, dR.z, dR.w};
    const float div[4] = {dI.x, dI.y, dI.z, dI.w};
    const float rdv[4] = {rd.x, rd.y, rd.z, rd.w};

    #pragma unroll
    for (int r = 0; r < RPB; r++) {
        const float sR = g_srcR[b*NN + i0 + r];
        const float sI = g_srcI[b*NN + i0 + r];

        float arr[4], aii[4];
        #pragma unroll
        for (int j = 0; j < 4; j++) {
            float sr = sR + drv[j];
            float si = sI + div[j];
            sr = sr >= 0.f ? sr : par*sr;
            si = si >= 0.f ? si : pai*si;
            float m2 = sr*sr + si*si;
            float rm = m2 > 0.f ? rsqrtf(m2) : 0.f;
            float e  = __expf(m2 * rm);
            float wq = e * rdv[j] * rm;
            arr[j] = wq * sr;
            aii[j] = wq * si;
        }
        const u64t ar01  = pk2(arr[0], arr[1]),  ar23  = pk2(arr[2], arr[3]);
        const u64t ai01  = pk2(aii[0], aii[1]),  ai23  = pk2(aii[2], aii[3]);
        const u64t nai01 = pk2(-aii[0], -aii[1]), nai23 = pk2(-aii[2], -aii[3]);

        // ---- load ALL 5 k rows (10 independent LDG.128 in flight) ----
        ulonglong2 lr[KP1], li[KP1];
        #pragma unroll
        for (int k = 0; k < KP1; k++) {
            size_t rowoff = ((size_t)((b*KP1 + k)*NN + (i0 + r))) * NN;
            lr[k] = ((const ulonglong2*)(L_r + rowoff))[t];
            li[k] = ((const ulonglong2*)(L_i + rowoff))[t];
        }

        // ---- FMA all k ----
        float aRs[KP1], aIs[KP1];
        #pragma unroll
        for (int k = 0; k < KP1; k++) {
            u64t aR2 = fma2(lr[k].x, ar01, 0ULL);
            aR2 = fma2(lr[k].y, ar23,  aR2);
            aR2 = fma2(li[k].x, nai01, aR2);
            aR2 = fma2(li[k].y, nai23, aR2);
            u64t aI2 = fma2(li[k].x, ar01, 0ULL);
            aI2 = fma2(li[k].y, ar23,  aI2);
            aI2 = fma2(lr[k].x, ai01,  aI2);
            aI2 = fma2(lr[k].y, ai23,  aI2);

            float lo, hi;
            upk2(aR2, lo, hi); aRs[k] = lo + hi;
            upk2(aI2, lo, hi); aIs[k] = lo + hi;
        }

        // ---- interleaved warp reduce: 10 independent chains per level ----
        #pragma unroll
        for (int off = 16; off > 0; off >>= 1) {
            #pragma unroll
            for (int k = 0; k < KP1; k++) {
                aRs[k] += __shfl_down_sync(0xFFFFFFFFu, aRs[k], off);
                aIs[k] += __shfl_down_sync(0xFFFFFFFFu, aIs[k], off);
            }
        }
        if (lane == 0) {
            #pragma unroll
            for (int k = 0; k < KP1; k++) {
                shPR[warp][r][k] = aRs[k];
                shPI[warp][r][k] = aIs[k];
            }
        }
    }
    __syncthreads();

    if (t < RPB*KP1) {
        int r = t / KP1, k = t - r*KP1;
        float SR = 0.f, SI = 0.f;
        #pragma unroll
        for (int w = 0; w < 8; w++) { SR += shPR[w][r][k]; SI += shPI[w][r][k]; }
        int row = b*NN + i0 + r;
        g_SLr[row*KP1 + k] = SR;
        g_SLi[row*KP1 + k] = SI;
    }
}

// ---------------------------------------------------------------------------
// Kernel 4 (epilogue): out[row,o] = sum_k SL[row,k] (x) Y[row,k,o] (R7 exact)
// ---------------------------------------------------------------------------
__global__ void __launch_bounds__(256)
k_epi(float* __restrict__ out)
{
    const int t   = threadIdx.x;
    const int row = blockIdx.x * RPB + (t >> 6);
    const int o   = t & 63;

    const float* yrr = g_Yrr + (size_t)row * YSTR + o;
    const float* yii = g_Yii + (size_t)row * YSTR + o;
    const float* slr = g_SLr + row*KP1;
    const float* sli = g_SLi + row*KP1;

    float or_ = 0.f, oi_ = 0.f;
    #pragma unroll
    for (int k = 0; k < KP1; k++) {
        float SR = slr[k], SI = sli[k];
        float yr = yrr[k*OC], yi = yii[k*OC];
        or_ += SR*yr - SI*yi;
        oi_ += SI*yr + SR*yi;
    }
    const size_t OUT_HALF = (size_t)ROWS * OC;
    size_t g = (size_t)row * OC + o;
    out[g]            = or_;
    out[OUT_HALF + g] = oi_;
}

// ---------------------------------------------------------------------------
extern "C" void kernel_launch(void* const* d_in, const int* in_sizes, int n_in,
                              void* d_out, int out_size)
{
    const float* Xr  = (const float*)d_in[0];
    const float* Xi  = (const float*)d_in[1];
    const float* Lr  = (const float*)d_in[2];
    const float* Li  = (const float*)d_in[3];
    const float* wr  = (const float*)d_in[4];
    const float* wi  = (const float*)d_in[5];
    const float* awr = (const float*)d_in[6];
    const float* awi = (const float*)d_in[7];
    const float* abr = (const float*)d_in[8];
    const float* abi = (const float*)d_in[9];
    const float* par = (const float*)d_in[10];
    const float* pai = (const float*)d_in[11];
    float* out = (float*)d_out;

    k_src  <<<ROWS/8, 256>>>(Xr, Xi, awr, awi, abr, abi);
    k_denom<<<ROWS/8, 256>>>(par, pai);
    k_fused<<<FUSED_BLKS, 256>>>(Lr, Li, Xr, Xi, wr, wi, par, pai);
    k_epi  <<<ROWS/RPB, 256>>>(out);
}

// round 15
// speedup vs baseline: 1.0207x; 1.0207x over previous
#include <cuda_runtime.h>
#include <cuda_bf16.h>

#define NB   8
#define NN   1024
#define NC   64
#define OC   64
#define KP1  5
#define RPB  4
#define ROWS (NB*NN)      // 8192
#define YSTR (KP1*OC)     // 320

#define STREAM_BLKS (ROWS/RPB)     // 2048
#define GEMM_BLKS   (128*KP1*2)    // 1280
#define FUSED_BLKS  (STREAM_BLKS + GEMM_BLKS)   // 3328

// Scratch (static device globals; no allocations allowed)
__device__ __align__(16) float g_srcR[ROWS];
__device__ __align__(16) float g_srcI[ROWS];
__device__ __align__(16) float g_dstR[ROWS];
__device__ __align__(16) float g_dstI[ROWS];
__device__ __align__(16) float g_rden[ROWS];
__device__ __align__(16) float g_Yrr[ROWS*YSTR];
__device__ __align__(16) float g_Yii[ROWS*YSTR];
__device__ __align__(16) float g_SLr[ROWS*KP1];
__device__ __align__(16) float g_SLi[ROWS*KP1];

// ---- packed fp32x2 helpers (sm_103a FFMA2) --------------------------------
typedef unsigned long long u64t;
__device__ __forceinline__ u64t pk2(float lo, float hi) {
    u64t d; asm("mov.b64 %0,{%1,%2};" : "=l"(d) : "f"(lo), "f"(hi)); return d;
}
__device__ __forceinline__ void upk2(u64t v, float& lo, float& hi) {
    asm("mov.b64 {%0,%1},%2;" : "=f"(lo), "=f"(hi) : "l"(v));
}
__device__ __forceinline__ u64t fma2(u64t a, u64t b, u64t c) {
    u64t d; asm("fma.rn.f32x2 %0,%1,%2,%3;" : "=l"(d) : "l"(a), "l"(b), "l"(c)); return d;
}

// ---------------------------------------------------------------------------
// Kernel 1: per-row complex projections. One warp per (b,n) row. (R7 exact)
// ---------------------------------------------------------------------------
__global__ void k_src(const float* __restrict__ Xr, const float* __restrict__ Xi,
                      const float* __restrict__ awr, const float* __restrict__ awi,
                      const float* __restrict__ abr, const float* __restrict__ abi)
{
    int gt   = blockIdx.x * blockDim.x + threadIdx.x;
    int warp = gt >> 5;
    int lane = gt & 31;
    if (warp >= ROWS) return;

    const float* xr = Xr + (size_t)warp * NC;
    const float* xi = Xi + (size_t)warp * NC;
    float xr0 = xr[lane], xr1 = xr[lane+32];
    float xi0 = xi[lane], xi1 = xi[lane+32];

    float wsr0 = awr[lane],    wsr1 = awr[lane+32];
    float wdr0 = awr[64+lane], wdr1 = awr[96+lane];
    float wsi0 = awi[lane],    wsi1 = awi[lane+32];
    float wdi0 = awi[64+lane], wdi1 = awi[96+lane];

    float sr = xr0*wsr0 + xr1*wsr1 - xi0*wsi0 - xi1*wsi1;
    float si = xr0*wsi0 + xr1*wsi1 + xi0*wsr0 + xi1*wsr1;
    float dr = xr0*wdr0 + xr1*wdr1 - xi0*wdi0 - xi1*wdi1;
    float di = xr0*wdi0 + xr1*wdi1 + xi0*wdr0 + xi1*wdr1;

    #pragma unroll
    for (int off = 16; off > 0; off >>= 1) {
        sr += __shfl_down_sync(0xFFFFFFFFu, sr, off);
        si += __shfl_down_sync(0xFFFFFFFFu, si, off);
        dr += __shfl_down_sync(0xFFFFFFFFu, dr, off);
        di += __shfl_down_sync(0xFFFFFFFFu, di, off);
    }
    if (lane == 0) {
        g_srcR[warp] = sr + *abr;
        g_srcI[warp] = si + *abi;
        g_dstR[warp] = dr;
        g_dstI[warp] = di;
    }
}

// ---------------------------------------------------------------------------
// Kernel 2: softmax denominators (axis i per (b,j)); stores reciprocal.
// ---------------------------------------------------------------------------
__global__ void k_denom(const float* __restrict__ par_p, const float* __restrict__ pai_p)
{
    int gt   = blockIdx.x * blockDim.x + threadIdx.x;
    int warp = gt >> 5;
    int lane = gt & 31;
    if (warp >= ROWS) return;

    int b = warp >> 10;
    float dr = g_dstR[warp], di = g_dstI[warp];
    float par = *par_p, pai = *pai_p;
    const float* sRp = g_srcR + b*NN;
    const float* sIp = g_srcI + b*NN;

    float acc = 0.f;
    #pragma unroll 4
    for (int i = lane; i < NN; i += 32) {
        float sr = sRp[i] + dr;
        float si = sIp[i] + di;
        sr = sr >= 0.f ? sr : par*sr;
        si = si >= 0.f ? si : pai*si;
        float m2  = sr*sr + si*si;
        float mag = m2 > 0.f ? m2 * rsqrtf(m2) : 0.f;
        acc += __expf(mag);
    }
    #pragma unroll
    for (int off = 16; off > 0; off >>= 1)
        acc += __shfl_down_sync(0xFFFFFFFFu, acc, off);
    if (lane == 0) g_rden[warp] = 1.0f / acc;
}

// ---------------------------------------------------------------------------
// Kernel 3 (fused): L-stream blocks interleaved with Y-GEMM blocks.
// Stream = R7 serial-k loop, but in-warp reduce cut to 2 shfl levels;
// lanes 0..7 store partials; final combine sums 8 warps x 8 lanes.
// ---------------------------------------------------------------------------
__global__ void __launch_bounds__(256, 4)
k_fused(const float* __restrict__ L_r, const float* __restrict__ L_i,
        const float* __restrict__ Xr,  const float* __restrict__ Xi,
        const float* __restrict__ wr,  const float* __restrict__ wi,
        const float* __restrict__ par_p, const float* __restrict__ pai_p)
{
    __shared__ __align__(16) float As[64][64];
    __shared__ __align__(16) float Ws[64][64];
    __shared__ float shPR[8][8][RPB][KP1];   // [warp][lane0..7][r][k]
    __shared__ float shPI[8][8][RPB][KP1];

    const int bid = blockIdx.x;
    const int t   = threadIdx.x;

    const int g0 = (int)(((long long)bid       * GEMM_BLKS) / FUSED_BLKS);
    const int g1 = (int)(((long long)(bid + 1) * GEMM_BLKS) / FUSED_BLKS);

    if (g1 > g0) {
        // ================= GEMM part: Y[n,k,o] = X @ w[k] =================
        const int gb   = g0;
        const int part = gb / (GEMM_BLKS/2);
        const int rem  = gb % (GEMM_BLKS/2);
        const int k    = rem / 128;
        const int n0   = (rem % 128) * 64;

        const float* A = part ? Xi : Xr;
        const float* W = (part ? wi : wr) + (size_t)k * NC * OC;
        float*       Y = part ? g_Yii : g_Yrr;

        for (int idx = t; idx < 64*64; idx += 256) {
            int r = idx >> 6, c = idx & 63;
            As[r][c] = A[(size_t)(n0 + r) * NC + c];
            ((float*)Ws)[idx] = W[idx];
        }
        __syncthreads();

        const int oq = t & 15;
        const int rg = t >> 4;

        u64t acc[4][2];
        #pragma unroll
        for (int rr = 0; rr < 4; rr++) { acc[rr][0] = 0ULL; acc[rr][1] = 0ULL; }

        #pragma unroll 8
        for (int c = 0; c < 64; c++) {
            ulonglong2 wv = *(const ulonglong2*)&Ws[c][oq*4];
            #pragma unroll
            for (int rr = 0; rr < 4; rr++) {
                float a  = As[rg*4 + rr][c];
                u64t  a2 = pk2(a, a);
                acc[rr][0] = fma2(a2, wv.x, acc[rr][0]);
                acc[rr][1] = fma2(a2, wv.y, acc[rr][1]);
            }
        }

        #pragma unroll
        for (int rr = 0; rr < 4; rr++) {
            float4 v;
            upk2(acc[rr][0], v.x, v.y);
            upk2(acc[rr][1], v.z, v.w);
            *(float4*)&Y[(size_t)(n0 + rg*4 + rr) * YSTR + k*OC + oq*4] = v;
        }
        return;
    }

    // ================= stream part =================
    const int sb   = bid - g0;
    const int b    = sb >> 8;
    const int i0   = (sb & 255) * RPB;
    const int warp = t >> 5;
    const int lane = t & 31;

    const float par = *par_p;
    const float pai = *pai_p;

    const float4 dR = ((const float4*)(g_dstR + b*NN))[t];
    const float4 dI = ((const float4*)(g_dstI + b*NN))[t];
    const float4 rd = ((const float4*)(g_rden + b*NN))[t];

    const float drv[4] = {dR.x, dR.y, dR.z, dR.w};
    const float div[4] = {dI.x, dI.y, dI.z, dI.w};
    const float rdv[4] = {rd.x, rd.y, rd.z, rd.w};

    #pragma unroll
    for (int r = 0; r < RPB; r++) {
        const float sR = g_srcR[b*NN + i0 + r];
        const float sI = g_srcI[b*NN + i0 + r];

        float arr[4], aii[4];
        #pragma unroll
        for (int j = 0; j < 4; j++) {
            float sr = sR + drv[j];
            float si = sI + div[j];
            sr = sr >= 0.f ? sr : par*sr;
            si = si >= 0.f ? si : pai*si;
            float m2 = sr*sr + si*si;
            float rm = m2 > 0.f ? rsqrtf(m2) : 0.f;
            float e  = __expf(m2 * rm);
            float wq = e * rdv[j] * rm;
            arr[j] = wq * sr;
            aii[j] = wq * si;
        }
        const u64t ar01  = pk2(arr[0], arr[1]),  ar23  = pk2(arr[2], arr[3]);
        const u64t ai01  = pk2(aii[0], aii[1]),  ai23  = pk2(aii[2], aii[3]);
        const u64t nai01 = pk2(-aii[0], -aii[1]), nai23 = pk2(-aii[2], -aii[3]);

        #pragma unroll
        for (int k = 0; k < KP1; k++) {
            size_t rowoff = ((size_t)((b*KP1 + k)*NN + (i0 + r))) * NN;
            const ulonglong2 lr = ((const ulonglong2*)(L_r + rowoff))[t];
            const ulonglong2 li = ((const ulonglong2*)(L_i + rowoff))[t];

            u64t aR2 = fma2(lr.x, ar01, 0ULL);
            aR2 = fma2(lr.y, ar23,  aR2);
            aR2 = fma2(li.x, nai01, aR2);
            aR2 = fma2(li.y, nai23, aR2);
            u64t aI2 = fma2(li.x, ar01, 0ULL);
            aI2 = fma2(li.y, ar23,  aI2);
            aI2 = fma2(lr.x, ai01,  aI2);
            aI2 = fma2(lr.y, ai23,  aI2);

            float lo, hi, aR, aI;
            upk2(aR2, lo, hi); aR = lo + hi;
            upk2(aI2, lo, hi); aI = lo + hi;

            // 2-level reduce only: lanes 0..7 hold partials (i, i+8, i+16, i+24)
            aR += __shfl_down_sync(0xFFFFFFFFu, aR, 16);
            aI += __shfl_down_sync(0xFFFFFFFFu, aI, 16);
            aR += __shfl_down_sync(0xFFFFFFFFu, aR, 8);
            aI += __shfl_down_sync(0xFFFFFFFFu, aI, 8);
            if (lane < 8) {
                shPR[warp][lane][r][k] = aR;
                shPI[warp][lane][r][k] = aI;
            }
        }
    }
    __syncthreads();

    // final combine: 20 (r,k) pairs, each sums 8 warps x 8 lanes
    if (t < RPB*KP1) {
        int r = t / KP1, k = t - r*KP1;
        float SR = 0.f, SI = 0.f;
        #pragma unroll
        for (int w = 0; w < 8; w++)
            #pragma unroll
            for (int l = 0; l < 8; l++) {
                SR += shPR[w][l][r][k];
                SI += shPI[w][l][r][k];
            }
        int row = b*NN + i0 + r;
        g_SLr[row*KP1 + k] = SR;
        g_SLi[row*KP1 + k] = SI;
    }
}

// ---------------------------------------------------------------------------
// Kernel 4 (epilogue): out[row,o] = sum_k SL[row,k] (x) Y[row,k,o] (R7 exact)
// ---------------------------------------------------------------------------
__global__ void __launch_bounds__(256)
k_epi(float* __restrict__ out)
{
    const int t   = threadIdx.x;
    const int row = blockIdx.x * RPB + (t >> 6);
    const int o   = t & 63;

    const float* yrr = g_Yrr + (size_t)row * YSTR + o;
    const float* yii = g_Yii + (size_t)row * YSTR + o;
    const float* slr = g_SLr + row*KP1;
    const float* sli = g_SLi + row*KP1;

    float or_ = 0.f, oi_ = 0.f;
    #pragma unroll
    for (int k = 0; k < KP1; k++) {
        float SR = slr[k], SI = sli[k];
        float yr = yrr[k*OC], yi = yii[k*OC];
        or_ += SR*yr - SI*yi;
        oi_ += SI*yr + SR*yi;
    }
    const size_t OUT_HALF = (size_t)ROWS * OC;
    size_t g = (size_t)row * OC + o;
    out[g]            = or_;
    out[OUT_HALF + g] = oi_;
}

// ---------------------------------------------------------------------------
extern "C" void kernel_launch(void* const* d_in, const int* in_sizes, int n_in,
                              void* d_out, int out_size)
{
    const float* Xr  = (const float*)d_in[0];
    const float* Xi  = (const float*)d_in[1];
    const float* Lr  = (const float*)d_in[2];
    const float* Li  = (const float*)d_in[3];
    const float* wr  = (const float*)d_in[4];
    const float* wi  = (const float*)d_in[5];
    const float* awr = (const float*)d_in[6];
    const float* awi = (const float*)d_in[7];
    const float* abr = (const float*)d_in[8];
    const float* abi = (const float*)d_in[9];
    const float* par = (const float*)d_in[10];
    const float* pai = (const float*)d_in[11];
    float* out = (float*)d_out;

    k_src  <<<ROWS/8, 256>>>(Xr, Xi, awr, awi, abr, abi);
    k_denom<<<ROWS/8, 256>>>(par, pai);
    k_fused<<<FUSED_BLKS, 256>>>(Lr, Li, Xr, Xi, wr, wi, par, pai);
    k_epi  <<<ROWS/RPB, 256>>>(out);
}

// round 16
// speedup vs baseline: 1.0347x; 1.0138x over previous
#include <cuda_runtime.h>
#include <cuda_bf16.h>

#define NB   8
#define NN   1024
#define NC   64
#define OC   64
#define KP1  5
#define RPB  4
#define ROWS (NB*NN)      // 8192
#define YSTR (KP1*OC)     // 320

#define STREAM_BLKS (ROWS/RPB)     // 2048
#define GEMM_BLKS   (128*KP1*2)    // 1280
#define FUSED_BLKS  (STREAM_BLKS + GEMM_BLKS)   // 3328

// Scratch (static device globals; no allocations allowed)
__device__ __align__(16) float g_srcR[ROWS];
__device__ __align__(16) float g_srcI[ROWS];
__device__ __align__(16) float g_dstR[ROWS];
__device__ __align__(16) float g_dstI[ROWS];
__device__ __align__(16) float g_rden[ROWS];
__device__ __align__(16) float g_Yrr[ROWS*YSTR];
__device__ __align__(16) float g_Yii[ROWS*YSTR];
__device__ __align__(16) float g_SLr[ROWS*KP1];
__device__ __align__(16) float g_SLi[ROWS*KP1];

// ---- packed fp32x2 helpers (sm_103a FFMA2) --------------------------------
typedef unsigned long long u64t;
__device__ __forceinline__ u64t pk2(float lo, float hi) {
    u64t d; asm("mov.b64 %0,{%1,%2};" : "=l"(d) : "f"(lo), "f"(hi)); return d;
}
__device__ __forceinline__ void upk2(u64t v, float& lo, float& hi) {
    asm("mov.b64 {%0,%1},%2;" : "=f"(lo), "=f"(hi) : "l"(v));
}
__device__ __forceinline__ u64t fma2(u64t a, u64t b, u64t c) {
    u64t d; asm("fma.rn.f32x2 %0,%1,%2,%3;" : "=l"(d) : "l"(a), "l"(b), "l"(c)); return d;
}

// ---------------------------------------------------------------------------
// Kernel 1: per-row complex projections. One warp per (b,n) row. (R7 exact)
// ---------------------------------------------------------------------------
__global__ void k_src(const float* __restrict__ Xr, const float* __restrict__ Xi,
                      const float* __restrict__ awr, const float* __restrict__ awi,
                      const float* __restrict__ abr, const float* __restrict__ abi)
{
    int gt   = blockIdx.x * blockDim.x + threadIdx.x;
    int warp = gt >> 5;
    int lane = gt & 31;
    if (warp >= ROWS) return;

    const float* xr = Xr + (size_t)warp * NC;
    const float* xi = Xi + (size_t)warp * NC;
    float xr0 = xr[lane], xr1 = xr[lane+32];
    float xi0 = xi[lane], xi1 = xi[lane+32];

    float wsr0 = awr[lane],    wsr1 = awr[lane+32];
    float wdr0 = awr[64+lane], wdr1 = awr[96+lane];
    float wsi0 = awi[lane],    wsi1 = awi[lane+32];
    float wdi0 = awi[64+lane], wdi1 = awi[96+lane];

    float sr = xr0*wsr0 + xr1*wsr1 - xi0*wsi0 - xi1*wsi1;
    float si = xr0*wsi0 + xr1*wsi1 + xi0*wsr0 + xi1*wsr1;
    float dr = xr0*wdr0 + xr1*wdr1 - xi0*wdi0 - xi1*wdi1;
    float di = xr0*wdi0 + xr1*wdi1 + xi0*wdr0 + xi1*wdr1;

    #pragma unroll
    for (int off = 16; off > 0; off >>= 1) {
        sr += __shfl_down_sync(0xFFFFFFFFu, sr, off);
        si += __shfl_down_sync(0xFFFFFFFFu, si, off);
        dr += __shfl_down_sync(0xFFFFFFFFu, dr, off);
        di += __shfl_down_sync(0xFFFFFFFFu, di, off);
    }
    if (lane == 0) {
        g_srcR[warp] = sr + *abr;
        g_srcI[warp] = si + *abi;
        g_dstR[warp] = dr;
        g_dstI[warp] = di;
    }
}

// ---------------------------------------------------------------------------
// Kernel 2: softmax denominators (axis i per (b,j)); stores reciprocal.
// ---------------------------------------------------------------------------
__global__ void k_denom(const float* __restrict__ par_p, const float* __restrict__ pai_p)
{
    int gt   = blockIdx.x * blockDim.x + threadIdx.x;
    int warp = gt >> 5;
    int lane = gt & 31;
    if (warp >= ROWS) return;

    int b = warp >> 10;
    float dr = g_dstR[warp], di = g_dstI[warp];
    float par = *par_p, pai = *pai_p;
    const float* sRp = g_srcR + b*NN;
    const float* sIp = g_srcI + b*NN;

    float acc = 0.f;
    #pragma unroll 4
    for (int i = lane; i < NN; i += 32) {
        float sr = sRp[i] + dr;
        float si = sIp[i] + di;
        sr = sr >= 0.f ? sr : par*sr;
        si = si >= 0.f ? si : pai*si;
        float m2  = sr*sr + si*si;
        float mag = m2 > 0.f ? m2 * rsqrtf(m2) : 0.f;
        acc += __expf(mag);
    }
    #pragma unroll
    for (int off = 16; off > 0; off >>= 1)
        acc += __shfl_down_sync(0xFFFFFFFFu, acc, off);
    if (lane == 0) g_rden[warp] = 1.0f / acc;
}

// ---------------------------------------------------------------------------
// Kernel 3 (fused): L-stream blocks interleaved with Y-GEMM blocks. (R12 exact)
// ---------------------------------------------------------------------------
__global__ void __launch_bounds__(256, 4)
k_fused(const float* __restrict__ L_r, const float* __restrict__ L_i,
        const float* __restrict__ Xr,  const float* __restrict__ Xi,
        const float* __restrict__ wr,  const float* __restrict__ wi,
        const float* __restrict__ par_p, const float* __restrict__ pai_p)
{
    __shared__ __align__(16) float As[64][64];
    __shared__ __align__(16) float Ws[64][64];
    __shared__ float shPR[8][RPB][KP1];
    __shared__ float shPI[8][RPB][KP1];

    const int bid = blockIdx.x;
    const int t   = threadIdx.x;

    const int g0 = (int)(((long long)bid       * GEMM_BLKS) / FUSED_BLKS);
    const int g1 = (int)(((long long)(bid + 1) * GEMM_BLKS) / FUSED_BLKS);

    if (g1 > g0) {
        // ================= GEMM part: Y[n,k,o] = X @ w[k] =================
        const int gb   = g0;
        const int part = gb / (GEMM_BLKS/2);
        const int rem  = gb % (GEMM_BLKS/2);
        const int k    = rem / 128;
        const int n0   = (rem % 128) * 64;

        const float* A = part ? Xi : Xr;
        const float* W = (part ? wi : wr) + (size_t)k * NC * OC;
        float*       Y = part ? g_Yii : g_Yrr;

        for (int idx = t; idx < 64*64; idx += 256) {
            int r = idx >> 6, c = idx & 63;
            As[r][c] = A[(size_t)(n0 + r) * NC + c];
            ((float*)Ws)[idx] = W[idx];
        }
        __syncthreads();

        const int oq = t & 15;
        const int rg = t >> 4;

        u64t acc[4][2];
        #pragma unroll
        for (int rr = 0; rr < 4; rr++) { acc[rr][0] = 0ULL; acc[rr][1] = 0ULL; }

        #pragma unroll 8
        for (int c = 0; c < 64; c++) {
            ulonglong2 wv = *(const ulonglong2*)&Ws[c][oq*4];
            #pragma unroll
            for (int rr = 0; rr < 4; rr++) {
                float a  = As[rg*4 + rr][c];
                u64t  a2 = pk2(a, a);
                acc[rr][0] = fma2(a2, wv.x, acc[rr][0]);
                acc[rr][1] = fma2(a2, wv.y, acc[rr][1]);
            }
        }

        #pragma unroll
        for (int rr = 0; rr < 4; rr++) {
            float4 v;
            upk2(acc[rr][0], v.x, v.y);
            upk2(acc[rr][1], v.z, v.w);
            *(float4*)&Y[(size_t)(n0 + rg*4 + rr) * YSTR + k*OC + oq*4] = v;
        }
        return;
    }

    // ================= stream part =================
    const int sb   = bid - g0;
    const int b    = sb >> 8;
    const int i0   = (sb & 255) * RPB;
    const int warp = t >> 5;
    const int lane = t & 31;

    const float par = *par_p;
    const float pai = *pai_p;

    const float4 dR = ((const float4*)(g_dstR + b*NN))[t];
    const float4 dI = ((const float4*)(g_dstI + b*NN))[t];
    const float4 rd = ((const float4*)(g_rden + b*NN))[t];

    const float drv[4] = {dR.x, dR.y, dR.z, dR.w};
    const float div[4] = {dI.x, dI.y, dI.z, dI.w};
    const float rdv[4] = {rd.x, rd.y, rd.z, rd.w};

    #pragma unroll
    for (int r = 0; r < RPB; r++) {
        const float sR = g_srcR[b*NN + i0 + r];
        const float sI = g_srcI[b*NN + i0 + r];

        float arr[4], aii[4];
        #pragma unroll
        for (int j = 0; j < 4; j++) {
            float sr = sR + drv[j];
            float si = sI + div[j];
            sr = sr >= 0.f ? sr : par*sr;
            si = si >= 0.f ? si : pai*si;
            float m2 = sr*sr + si*si;
            float rm = m2 > 0.f ? rsqrtf(m2) : 0.f;
            float e  = __expf(m2 * rm);
            float wq = e * rdv[j] * rm;
            arr[j] = wq * sr;
            aii[j] = wq * si;
        }
        const u64t ar01  = pk2(arr[0], arr[1]),  ar23  = pk2(arr[2], arr[3]);
        const u64t ai01  = pk2(aii[0], aii[1]),  ai23  = pk2(aii[2], aii[3]);
        const u64t nai01 = pk2(-aii[0], -aii[1]), nai23 = pk2(-aii[2], -aii[3]);

        #pragma unroll
        for (int k = 0; k < KP1; k++) {
            size_t rowoff = ((size_t)((b*KP1 + k)*NN + (i0 + r))) * NN;
            const ulonglong2 lr = ((const ulonglong2*)(L_r + rowoff))[t];
            const ulonglong2 li = ((const ulonglong2*)(L_i + rowoff))[t];

            u64t aR2 = fma2(lr.x, ar01, 0ULL);
            aR2 = fma2(lr.y, ar23,  aR2);
            aR2 = fma2(li.x, nai01, aR2);
            aR2 = fma2(li.y, nai23, aR2);
            u64t aI2 = fma2(li.x, ar01, 0ULL);
            aI2 = fma2(li.y, ar23,  aI2);
            aI2 = fma2(lr.x, ai01,  aI2);
            aI2 = fma2(lr.y, ai23,  aI2);

            float lo, hi, aR, aI;
            upk2(aR2, lo, hi); aR = lo + hi;
            upk2(aI2, lo, hi); aI = lo + hi;
            #pragma unroll
            for (int off = 16; off > 0; off >>= 1) {
                aR += __shfl_down_sync(0xFFFFFFFFu, aR, off);
                aI += __shfl_down_sync(0xFFFFFFFFu, aI, off);
            }
            if (lane == 0) {
                shPR[warp][r][k] = aR;
                shPI[warp][r][k] = aI;
            }
        }
    }
    __syncthreads();

    if (t < RPB*KP1) {
        int r = t / KP1, k = t - r*KP1;
        float SR = 0.f, SI = 0.f;
        #pragma unroll
        for (int w = 0; w < 8; w++) { SR += shPR[w][r][k]; SI += shPI[w][r][k]; }
        int row = b*NN + i0 + r;
        g_SLr[row*KP1 + k] = SR;
        g_SLi[row*KP1 + k] = SI;
    }
}

// ---------------------------------------------------------------------------
// Kernel 4 (epilogue): out[row,o] = sum_k SL[row,k] (x) Y[row,k,o]
// float4 per thread: thread = (row, o-quad); 10 independent 16B loads.
// grid = 512 blocks x 256 threads; 16 rows per block.
// ---------------------------------------------------------------------------
__global__ void __launch_bounds__(256)
k_epi(float* __restrict__ out)
{
    const int t   = threadIdx.x;
    const int oq  = t & 15;                 // o = 4*oq .. 4*oq+3
    const int row = blockIdx.x * 16 + (t >> 4);

    const float* yr_base = g_Yrr + (size_t)row * YSTR;
    const float* yi_base = g_Yii + (size_t)row * YSTR;
    const float* slr = g_SLr + row*KP1;
    const float* sli = g_SLi + row*KP1;

    // preload all 10 float4 (independent) + 10 scalars
    float4 yr[KP1], yi[KP1];
    #pragma unroll
    for (int k = 0; k < KP1; k++) {
        yr[k] = ((const float4*)(yr_base + k*OC))[oq];
        yi[k] = ((const float4*)(yi_base + k*OC))[oq];
    }

    float4 oR = make_float4(0.f,0.f,0.f,0.f);
    float4 oI = make_float4(0.f,0.f,0.f,0.f);
    #pragma unroll
    for (int k = 0; k < KP1; k++) {
        float SR = slr[k], SI = sli[k];
        oR.x += SR*yr[k].x - SI*yi[k].x;
        oR.y += SR*yr[k].y - SI*yi[k].y;
        oR.z += SR*yr[k].z - SI*yi[k].z;
        oR.w += SR*yr[k].w - SI*yi[k].w;
        oI.x += SI*yr[k].x + SR*yi[k].x;
        oI.y += SI*yr[k].y + SR*yi[k].y;
        oI.z += SI*yr[k].z + SR*yi[k].z;
        oI.w += SI*yr[k].w + SR*yi[k].w;
    }

    const size_t OUT_HALF = (size_t)ROWS * OC;
    ((float4*)(out + (size_t)row * OC))[oq]            = oR;
    ((float4*)(out + OUT_HALF + (size_t)row * OC))[oq] = oI;
}

// ---------------------------------------------------------------------------
extern "C" void kernel_launch(void* const* d_in, const int* in_sizes, int n_in,
                              void* d_out, int out_size)
{
    const float* Xr  = (const float*)d_in[0];
    const float* Xi  = (const float*)d_in[1];
    const float* Lr  = (const float*)d_in[2];
    const float* Li  = (const float*)d_in[3];
    const float* wr  = (const float*)d_in[4];
    const float* wi  = (const float*)d_in[5];
    const float* awr = (const float*)d_in[6];
    const float* awi = (const float*)d_in[7];
    const float* abr = (const float*)d_in[8];
    const float* abi = (const float*)d_in[9];
    const float* par = (const float*)d_in[10];
    const float* pai = (const float*)d_in[11];
    float* out = (float*)d_out;

    k_src  <<<ROWS/8, 256>>>(Xr, Xi, awr, awi, abr, abi);
    k_denom<<<ROWS/8, 256>>>(par, pai);
    k_fused<<<FUSED_BLKS, 256>>>(Lr, Li, Xr, Xi, wr, wi, par, pai);
    k_epi  <<<ROWS/16, 256>>>(out);
}